// round 1
// baseline (speedup 1.0000x reference)
#include <cuda_runtime.h>
#include <cuda_bf16.h>
#include <math_constants.h>

// ---------------- problem constants ----------------
#define NN 16384      // nodes
#define GG 256        // graphs
#define NPG 64        // nodes per graph
#define HH 8          // heads
#define FF 64         // per-head features
#define DD 512        // H*F
#define EMAX 147456   // edges incl self loops

// ---------------- scratch (device globals; no allocs allowed) ----------------
__device__ float g_XL[NN * DD];
__device__ float g_XR[NN * DD];
__device__ float g_A [NN * DD];
__device__ float g_B [NN * DD];
__device__ int   g_cnt [NN];
__device__ int   g_row [NN + 1];
__device__ int   g_fill[NN];
__device__ int   g_csrc[EMAX];

// ---------------- tiny utility kernels ----------------
__global__ void zero_int_kernel(int* p, int n) {
    int i = blockIdx.x * blockDim.x + threadIdx.x;
    if (i < n) p[i] = 0;
}

__global__ void count_kernel(const int* __restrict__ dst, int E, int* __restrict__ cnt) {
    int e = blockIdx.x * blockDim.x + threadIdx.x;
    if (e < E) atomicAdd(&cnt[dst[e]], 1);
}

// single-block exclusive scan over NN=16384 counts (1024 threads x 16 each)
__global__ void scan_kernel(const int* __restrict__ cnt, int* __restrict__ row,
                            int* __restrict__ fill) {
    __shared__ int s[1024];
    int tid = threadIdx.x;
    int base = tid * 16;
    int local[16];
    int sum = 0;
#pragma unroll
    for (int i = 0; i < 16; i++) { local[i] = sum; sum += cnt[base + i]; }
    s[tid] = sum;
    __syncthreads();
    // Hillis-Steele inclusive scan
    for (int off = 1; off < 1024; off <<= 1) {
        int v = (tid >= off) ? s[tid - off] : 0;
        __syncthreads();
        s[tid] += v;
        __syncthreads();
    }
    int pre = (tid == 0) ? 0 : s[tid - 1];
#pragma unroll
    for (int i = 0; i < 16; i++) {
        int o = pre + local[i];
        row[base + i]  = o;
        fill[base + i] = o;
    }
    if (tid == 1023) row[NN] = s[1023];
}

__global__ void scatter_kernel(const int* __restrict__ src, const int* __restrict__ dst,
                               int E, int* __restrict__ fill, int* __restrict__ csrc) {
    int e = blockIdx.x * blockDim.x + threadIdx.x;
    if (e < E) {
        int p = atomicAdd(&fill[dst[e]], 1);
        csrc[p] = src[e];
    }
}

// ---------------- SGEMM: C[M,N] = A[M,K] @ B[K,N], fp32, exact tile sizes ----------------
// BM=128, BN=128, BK=8, 256 threads, 8x8 per-thread microtile.
__global__ __launch_bounds__(256, 2)
void sgemm_kernel(int M, int N, int K,
                  const float* __restrict__ A, const float* __restrict__ B,
                  float* __restrict__ C) {
    const int BM = 128, BN = 128, BK = 8, TM = 8, TN = 8;
    __shared__ float As[BK][BM];
    __shared__ float Bs[BK][BN];
    const int tid = threadIdx.x;
    const int brow = blockIdx.y, bcol = blockIdx.x;
    const float* Ab = A + (size_t)brow * BM * K;
    const float* Bb = B + bcol * BN;

    float acc[TM][TN] = {};
    const int aRow = tid >> 1, aCol = (tid & 1) << 2;        // 128 rows x 2 float4
    const int bRow = tid >> 5, bCol = (tid & 31) << 2;       // 8 rows x 32 float4
    const int tRow = (tid >> 4) * TM, tCol = (tid & 15) * TN;

    for (int k0 = 0; k0 < K; k0 += BK) {
        float4 a4 = *(const float4*)(Ab + (size_t)aRow * K + k0 + aCol);
        As[aCol + 0][aRow] = a4.x;
        As[aCol + 1][aRow] = a4.y;
        As[aCol + 2][aRow] = a4.z;
        As[aCol + 3][aRow] = a4.w;
        float4 b4 = *(const float4*)(Bb + (size_t)(k0 + bRow) * N + bCol);
        *(float4*)(&Bs[bRow][bCol]) = b4;
        __syncthreads();
#pragma unroll
        for (int k = 0; k < BK; k++) {
            float ra[TM], rb[TN];
#pragma unroll
            for (int i = 0; i < TM; i++) ra[i] = As[k][tRow + i];
#pragma unroll
            for (int j = 0; j < TN; j++) rb[j] = Bs[k][tCol + j];
#pragma unroll
            for (int i = 0; i < TM; i++)
#pragma unroll
                for (int j = 0; j < TN; j++)
                    acc[i][j] += ra[i] * rb[j];
        }
        __syncthreads();
    }
#pragma unroll
    for (int i = 0; i < TM; i++)
#pragma unroll
        for (int j = 0; j < TN; j += 4) {
            float4 v = make_float4(acc[i][j], acc[i][j + 1], acc[i][j + 2], acc[i][j + 3]);
            *(float4*)(C + (size_t)(brow * BM + tRow + i) * N + bcol * BN + tCol + j) = v;
        }
}

// ---------------- fused GATv2 attention + online-softmax aggregation ----------------
// one warp per destination node. lane l: head h=l>>2, features fb..fb+15 (fb = h*64 + (l&3)*16)
__global__ __launch_bounds__(256)
void gat_agg_kernel(const float* __restrict__ xl, const float* __restrict__ xr,
                    const int* __restrict__ row, const int* __restrict__ csrc,
                    const float* __restrict__ att, const float* __restrict__ bias,
                    float* __restrict__ out, int concat) {
    int warp = (blockIdx.x * blockDim.x + threadIdx.x) >> 5;
    int lane = threadIdx.x & 31;
    int fb = ((lane >> 2) << 6) + ((lane & 3) << 4);

    float attr[16], xrr[16], acc[16];
    {
        const float4* ap = (const float4*)(att + fb);
        const float4* rp = (const float4*)(xr + (size_t)warp * DD + fb);
#pragma unroll
        for (int q = 0; q < 4; q++) {
            float4 a = ap[q];
            attr[q * 4 + 0] = a.x; attr[q * 4 + 1] = a.y; attr[q * 4 + 2] = a.z; attr[q * 4 + 3] = a.w;
            float4 r = rp[q];
            xrr[q * 4 + 0] = r.x; xrr[q * 4 + 1] = r.y; xrr[q * 4 + 2] = r.z; xrr[q * 4 + 3] = r.w;
        }
    }
#pragma unroll
    for (int k = 0; k < 16; k++) acc[k] = 0.f;

    float m = -CUDART_INF_F, den = 0.f;
    int j0 = row[warp], j1 = row[warp + 1];

    for (int j = j0; j < j1; j++) {
        int s = csrc[j];
        float xlv[16];
        const float4* lp = (const float4*)(xl + (size_t)s * DD + fb);
#pragma unroll
        for (int q = 0; q < 4; q++) {
            float4 v = lp[q];
            xlv[q * 4 + 0] = v.x; xlv[q * 4 + 1] = v.y; xlv[q * 4 + 2] = v.z; xlv[q * 4 + 3] = v.w;
        }
        float p = 0.f;
#pragma unroll
        for (int k = 0; k < 16; k++) {
            float t = xlv[k] + xrr[k];
            t = (t > 0.f) ? t : 0.2f * t;   // leaky relu
            p += attr[k] * t;
        }
        // reduce over the 4 lanes of this head (xor within aligned group of 4)
        p += __shfl_xor_sync(0xffffffffu, p, 1);
        p += __shfl_xor_sync(0xffffffffu, p, 2);
        // online softmax update
        float mn = fmaxf(m, p);
        float scale = __expf(m - mn);   // 0 on first edge (m=-inf)
        float w = __expf(p - mn);
        den = den * scale + w;
#pragma unroll
        for (int k = 0; k < 16; k++) acc[k] = acc[k] * scale + w * xlv[k];
        m = mn;
    }

    float inv = 1.f / (den + 1e-16f);
    if (concat) {
        float* op = out + (size_t)warp * DD + fb;
#pragma unroll
        for (int q = 0; q < 4; q++) {
            float4 v;
            v.x = acc[q * 4 + 0] * inv + bias[fb + q * 4 + 0];
            v.y = acc[q * 4 + 1] * inv + bias[fb + q * 4 + 1];
            v.z = acc[q * 4 + 2] * inv + bias[fb + q * 4 + 2];
            v.w = acc[q * 4 + 3] * inv + bias[fb + q * 4 + 3];
            *(float4*)(op + q * 4) = v;
        }
    } else {
        float r[16];
#pragma unroll
        for (int k = 0; k < 16; k++) r[k] = acc[k] * inv;
        // sum over heads: lanes with same (l&3) across the 8 head groups
#pragma unroll
        for (int off = 4; off < 32; off <<= 1)
#pragma unroll
            for (int k = 0; k < 16; k++) r[k] += __shfl_xor_sync(0xffffffffu, r[k], off);
        if (lane < 4) {
            int fo = lane << 4;
            float* op = out + (size_t)warp * FF + fo;
#pragma unroll
            for (int k = 0; k < 16; k++)
                op[k] = r[k] * 0.125f + bias[fo + k];
        }
    }
}

// ---------------- GraphNorm + ReLU (contiguous 64-node graphs) ----------------
__global__ void graphnorm_relu_kernel(const float* __restrict__ in, const float* __restrict__ w,
                                      const float* __restrict__ b, const float* __restrict__ ms,
                                      float* __restrict__ out, int D) {
    int g = blockIdx.x;
    const float* base = in + (size_t)g * NPG * D;
    float* ob = out + (size_t)g * NPG * D;
    for (int d = threadIdx.x; d < D; d += blockDim.x) {
        float s = 0.f;
#pragma unroll 8
        for (int i = 0; i < NPG; i++) s += base[(size_t)i * D + d];
        float mean = s * (1.f / NPG);
        float msm = ms[d] * mean;
        float v = 0.f;
#pragma unroll 8
        for (int i = 0; i < NPG; i++) { float xc = base[(size_t)i * D + d] - msm; v += xc * xc; }
        v *= (1.f / NPG);
        float invs = rsqrtf(v + 1e-5f);
        float ww = w[d], bb = b[d];
#pragma unroll 8
        for (int i = 0; i < NPG; i++) {
            float xc = base[(size_t)i * D + d] - msm;
            float o = ww * xc * invs + bb;
            ob[(size_t)i * D + d] = fmaxf(o, 0.f);
        }
    }
}

// ---------------- global mean pool + final linear ----------------
__global__ void pool_linear_kernel(const float* __restrict__ h, const float* __restrict__ Wlin,
                                   const float* __restrict__ blin, float* __restrict__ out) {
    int g = blockIdx.x;
    __shared__ float p[FF];
    int t = threadIdx.x;  // 64 threads, one per feature
    float s = 0.f;
#pragma unroll 8
    for (int i = 0; i < NPG; i++) s += h[(size_t)(g * NPG + i) * FF + t];
    p[t] = s * (1.f / NPG);
    __syncthreads();
    if (t < 2) {
        float o = blin[t];
#pragma unroll
        for (int f = 0; f < FF; f++) o += p[f] * Wlin[f * 2 + t];
        out[g * 2 + t] = o;
    }
}

// ---------------- host launcher ----------------
extern "C" void kernel_launch(void* const* d_in, const int* in_sizes, int n_in,
                              void* d_out, int out_size) {
    const float* x     = (const float*)d_in[0];
    const int*   esrc  = (const int*)d_in[1];
    const int*   edst  = (const int*)d_in[2];
    // d_in[3] batch: unused (graphs are contiguous 64-node blocks)
    const float* Wl[3]  = {(const float*)d_in[4],  (const float*)d_in[11], (const float*)d_in[18]};
    const float* Wr[3]  = {(const float*)d_in[5],  (const float*)d_in[12], (const float*)d_in[19]};
    const float* att[3] = {(const float*)d_in[6],  (const float*)d_in[13], (const float*)d_in[20]};
    const float* bia[3] = {(const float*)d_in[7],  (const float*)d_in[14], (const float*)d_in[21]};
    const float* gnw[3] = {(const float*)d_in[8],  (const float*)d_in[15], (const float*)d_in[22]};
    const float* gnb[3] = {(const float*)d_in[9],  (const float*)d_in[16], (const float*)d_in[23]};
    const float* gnm[3] = {(const float*)d_in[10], (const float*)d_in[17], (const float*)d_in[24]};
    const float* Wlin = (const float*)d_in[25];
    const float* blin = (const float*)d_in[26];
    float* out = (float*)d_out;

    int E = in_sizes[1];

    float *XL, *XR, *A, *B;
    int *cnt, *row, *fill, *csrc;
    cudaGetSymbolAddress((void**)&XL,  g_XL);
    cudaGetSymbolAddress((void**)&XR,  g_XR);
    cudaGetSymbolAddress((void**)&A,   g_A);
    cudaGetSymbolAddress((void**)&B,   g_B);
    cudaGetSymbolAddress((void**)&cnt, g_cnt);
    cudaGetSymbolAddress((void**)&row, g_row);
    cudaGetSymbolAddress((void**)&fill,g_fill);
    cudaGetSymbolAddress((void**)&csrc,g_csrc);

    // ---- build dst-keyed CSR ----
    zero_int_kernel<<<(NN + 255) / 256, 256>>>(cnt, NN);
    count_kernel<<<(E + 255) / 256, 256>>>(edst, E, cnt);
    scan_kernel<<<1, 1024>>>(cnt, row, fill);
    scatter_kernel<<<(E + 255) / 256, 256>>>(esrc, edst, E, fill, csrc);

    dim3 gemm_grid(DD / 128, NN / 128);   // (4, 128)
    const int agg_blocks = (NN * 32) / 256;  // 2048

    // ---- layer 1 (K=256) ----
    sgemm_kernel<<<gemm_grid, 256>>>(NN, DD, 256, x, Wl[0], XL);
    sgemm_kernel<<<gemm_grid, 256>>>(NN, DD, 256, x, Wr[0], XR);
    gat_agg_kernel<<<agg_blocks, 256>>>(XL, XR, row, csrc, att[0], bia[0], A, 1);
    graphnorm_relu_kernel<<<GG, 256>>>(A, gnw[0], gnb[0], gnm[0], B, DD);

    // ---- layer 2 (K=512) ----
    sgemm_kernel<<<gemm_grid, 256>>>(NN, DD, DD, B, Wl[1], XL);
    sgemm_kernel<<<gemm_grid, 256>>>(NN, DD, DD, B, Wr[1], XR);
    gat_agg_kernel<<<agg_blocks, 256>>>(XL, XR, row, csrc, att[1], bia[1], A, 1);
    graphnorm_relu_kernel<<<GG, 256>>>(A, gnw[1], gnb[1], gnm[1], B, DD);

    // ---- layer 3 (K=512, concat=False) ----
    sgemm_kernel<<<gemm_grid, 256>>>(NN, DD, DD, B, Wl[2], XL);
    sgemm_kernel<<<gemm_grid, 256>>>(NN, DD, DD, B, Wr[2], XR);
    gat_agg_kernel<<<agg_blocks, 256>>>(XL, XR, row, csrc, att[2], bia[2], A, 0);
    graphnorm_relu_kernel<<<GG, 256>>>(A, gnw[2], gnb[2], gnm[2], B, FF);

    // ---- pool + linear ----
    pool_linear_kernel<<<GG, 64>>>(B, Wlin, blin, out);
}

// round 2
// speedup vs baseline: 2.3123x; 2.3123x over previous
#include <cuda_runtime.h>
#include <cuda_bf16.h>
#include <math_constants.h>
#include <cstdint>

// ---------------- problem constants ----------------
#define NN 16384      // nodes
#define GG 256        // graphs
#define NPG 64        // nodes per graph
#define HH 8          // heads
#define FF 64         // per-head features
#define DD 512        // H*F
#define EMAX 147456   // edges incl self loops

// ---------------- scratch (device globals; no allocs allowed) ----------------
__device__ float g_XL[NN * DD];
__device__ float g_XR[NN * DD];
__device__ float g_A [NN * DD];
__device__ float g_B [NN * DD];
__device__ float g_Xr[NN * 256];        // tf32-rounded input x
__device__ float g_Wr[1310720];         // tf32-rounded weights (6 matrices)
__device__ int   g_cnt [NN];
__device__ int   g_row [NN + 1];
__device__ int   g_fill[NN];
__device__ int   g_csrc[EMAX];

// ---------------- tf32 rounding ----------------
__device__ __forceinline__ float rtf32(float x) {
    uint32_t o; asm("cvt.rna.tf32.f32 %0, %1;" : "=r"(o) : "f"(x));
    return __uint_as_float(o);
}

__global__ void round4_kernel(const float4* __restrict__ in, float4* __restrict__ out, int n4) {
    int i = blockIdx.x * blockDim.x + threadIdx.x;
    if (i < n4) {
        float4 v = in[i];
        v.x = rtf32(v.x); v.y = rtf32(v.y); v.z = rtf32(v.z); v.w = rtf32(v.w);
        out[i] = v;
    }
}

// ---------------- tiny utility kernels (CSR build) ----------------
__global__ void zero_int_kernel(int* p, int n) {
    int i = blockIdx.x * blockDim.x + threadIdx.x;
    if (i < n) p[i] = 0;
}

__global__ void count_kernel(const int* __restrict__ dst, int E, int* __restrict__ cnt) {
    int e = blockIdx.x * blockDim.x + threadIdx.x;
    if (e < E) atomicAdd(&cnt[dst[e]], 1);
}

__global__ void scan_kernel(const int* __restrict__ cnt, int* __restrict__ row,
                            int* __restrict__ fill) {
    __shared__ int s[1024];
    int tid = threadIdx.x;
    int base = tid * 16;
    int local[16];
    int sum = 0;
#pragma unroll
    for (int i = 0; i < 16; i++) { local[i] = sum; sum += cnt[base + i]; }
    s[tid] = sum;
    __syncthreads();
    for (int off = 1; off < 1024; off <<= 1) {
        int v = (tid >= off) ? s[tid - off] : 0;
        __syncthreads();
        s[tid] += v;
        __syncthreads();
    }
    int pre = (tid == 0) ? 0 : s[tid - 1];
#pragma unroll
    for (int i = 0; i < 16; i++) {
        int o = pre + local[i];
        row[base + i]  = o;
        fill[base + i] = o;
    }
    if (tid == 1023) row[NN] = s[1023];
}

__global__ void scatter_kernel(const int* __restrict__ src, const int* __restrict__ dst,
                               int E, int* __restrict__ fill, int* __restrict__ csrc) {
    int e = blockIdx.x * blockDim.x + threadIdx.x;
    if (e < E) {
        int p = atomicAdd(&fill[dst[e]], 1);
        csrc[p] = src[e];
    }
}

// ---------------- tensor-core tf32 GEMM ----------------
// C[M, 512] = A[M, K] @ B[K, 512]; tiles 128x128x16, 256 threads,
// 8 warps in 2(m) x 4(n), warp tile 64x32, mma.m16n8k8.tf32.
__device__ __forceinline__ void cp16(uint32_t d, const void* s) {
    asm volatile("cp.async.cg.shared.global [%0], [%1], 16;" :: "r"(d), "l"(s));
}

__global__ __launch_bounds__(256, 2)
void tc_gemm_kernel(int K, const float* __restrict__ A, const float* __restrict__ B,
                    float* __restrict__ C) {
    __shared__ float As[2][128][20];   // [m][k], stride 20 -> conflict-free ldmatrix
    __shared__ float Bs[2][16][136];   // [k][n], stride 136 -> conflict-free LDS

    const int tid  = threadIdx.x;
    const int lane = tid & 31;
    const int warp = tid >> 5;
    const int wm = (warp >> 2) << 6;   // 0 / 64
    const int wn = (warp & 3) << 5;    // 0 / 32 / 64 / 96
    const int bm = blockIdx.y << 7;
    const int bn = blockIdx.x << 7;
    const int g = lane >> 2, t = lane & 3;

    // cp.async source/dest assignments
    const int arow = tid >> 2, aq = (tid & 3) << 2;    // A rows arow, arow+64
    const int brow = tid >> 5, bq = (tid & 31) << 2;   // B rows brow, brow+8
    const float* Ag0 = A + (size_t)(bm + arow)      * K + aq;
    const float* Ag1 = A + (size_t)(bm + arow + 64) * K + aq;
    const float* Bg0 = B + (size_t)brow       * DD + bn + bq;
    const float* Bg1 = B + (size_t)(brow + 8) * DD + bn + bq;

    const uint32_t sAs = (uint32_t)__cvta_generic_to_shared(&As[0][0][0]);
    const uint32_t sBs = (uint32_t)__cvta_generic_to_shared(&Bs[0][0][0]);
    const uint32_t aDst0 = sAs + (arow * 20 + aq) * 4;
    const uint32_t aDst1 = sAs + ((arow + 64) * 20 + aq) * 4;
    const uint32_t bDst0 = sBs + (brow * 136 + bq) * 4;
    const uint32_t bDst1 = sBs + ((brow + 8) * 136 + bq) * 4;

#define LOADTILE(buf, k0) do {                                     \
        cp16(aDst0 + (buf) * (128*20*4), Ag0 + (k0));              \
        cp16(aDst1 + (buf) * (128*20*4), Ag1 + (k0));              \
        cp16(bDst0 + (buf) * (16*136*4), Bg0 + (size_t)(k0) * DD); \
        cp16(bDst1 + (buf) * (16*136*4), Bg1 + (size_t)(k0) * DD); \
    } while (0)

    float c[4][4][4] = {};

    LOADTILE(0, 0);
    asm volatile("cp.async.commit_group;");

    const int KT = K >> 4;
    int buf = 0;
    const int aRow = wm + (lane & 15);
    const int aColHalf = (lane >> 4) << 2;

    for (int kt = 0; kt < KT; kt++) {
        if (kt + 1 < KT) {
            LOADTILE(buf ^ 1, (kt + 1) << 4);
            asm volatile("cp.async.commit_group;");
            asm volatile("cp.async.wait_group 1;");
        } else {
            asm volatile("cp.async.wait_group 0;");
        }
        __syncthreads();

        const uint32_t aBase = sAs + buf * (128 * 20 * 4);
        const float (*BsBuf)[136] = Bs[buf];
#pragma unroll
        for (int ks = 0; ks < 2; ks++) {
            uint32_t a[4][4];
#pragma unroll
            for (int mt = 0; mt < 4; mt++) {
                uint32_t addr = aBase + (((aRow + mt * 16) * 20) + ks * 8 + aColHalf) * 4;
                asm volatile("ldmatrix.sync.aligned.m8n8.x4.shared.b16 {%0,%1,%2,%3}, [%4];"
                    : "=r"(a[mt][0]), "=r"(a[mt][1]), "=r"(a[mt][2]), "=r"(a[mt][3])
                    : "r"(addr));
            }
            uint32_t bf[4][2];
#pragma unroll
            for (int nt = 0; nt < 4; nt++) {
                bf[nt][0] = __float_as_uint(BsBuf[ks * 8 + t    ][wn + nt * 8 + g]);
                bf[nt][1] = __float_as_uint(BsBuf[ks * 8 + t + 4][wn + nt * 8 + g]);
            }
#pragma unroll
            for (int mt = 0; mt < 4; mt++)
#pragma unroll
                for (int nt = 0; nt < 4; nt++)
                    asm volatile(
                        "mma.sync.aligned.m16n8k8.row.col.f32.tf32.tf32.f32 "
                        "{%0,%1,%2,%3},{%4,%5,%6,%7},{%8,%9},{%0,%1,%2,%3};"
                        : "+f"(c[mt][nt][0]), "+f"(c[mt][nt][1]),
                          "+f"(c[mt][nt][2]), "+f"(c[mt][nt][3])
                        : "r"(a[mt][0]), "r"(a[mt][1]), "r"(a[mt][2]), "r"(a[mt][3]),
                          "r"(bf[nt][0]), "r"(bf[nt][1]));
        }
        __syncthreads();
        buf ^= 1;
    }
#undef LOADTILE

    // epilogue
#pragma unroll
    for (int mt = 0; mt < 4; mt++) {
        int r0 = bm + wm + mt * 16 + g;
#pragma unroll
        for (int nt = 0; nt < 4; nt++) {
            int col = bn + wn + nt * 8 + 2 * t;
            *(float2*)(C + (size_t)r0 * DD + col)       = make_float2(c[mt][nt][0], c[mt][nt][1]);
            *(float2*)(C + (size_t)(r0 + 8) * DD + col) = make_float2(c[mt][nt][2], c[mt][nt][3]);
        }
    }
}

// ---------------- fused GATv2 attention + online-softmax aggregation ----------------
__global__ __launch_bounds__(256)
void gat_agg_kernel(const float* __restrict__ xl, const float* __restrict__ xr,
                    const int* __restrict__ row, const int* __restrict__ csrc,
                    const float* __restrict__ att, const float* __restrict__ bias,
                    float* __restrict__ out, int concat) {
    int warp = (blockIdx.x * blockDim.x + threadIdx.x) >> 5;
    int lane = threadIdx.x & 31;
    int fb = ((lane >> 2) << 6) + ((lane & 3) << 4);

    float attr[16], xrr[16], acc[16];
    {
        const float4* ap = (const float4*)(att + fb);
        const float4* rp = (const float4*)(xr + (size_t)warp * DD + fb);
#pragma unroll
        for (int q = 0; q < 4; q++) {
            float4 a = ap[q];
            attr[q * 4 + 0] = a.x; attr[q * 4 + 1] = a.y; attr[q * 4 + 2] = a.z; attr[q * 4 + 3] = a.w;
            float4 r = rp[q];
            xrr[q * 4 + 0] = r.x; xrr[q * 4 + 1] = r.y; xrr[q * 4 + 2] = r.z; xrr[q * 4 + 3] = r.w;
        }
    }
#pragma unroll
    for (int k = 0; k < 16; k++) acc[k] = 0.f;

    float m = -CUDART_INF_F, den = 0.f;
    int j0 = row[warp], j1 = row[warp + 1];

    for (int j = j0; j < j1; j++) {
        int s = csrc[j];
        float xlv[16];
        const float4* lp = (const float4*)(xl + (size_t)s * DD + fb);
#pragma unroll
        for (int q = 0; q < 4; q++) {
            float4 v = lp[q];
            xlv[q * 4 + 0] = v.x; xlv[q * 4 + 1] = v.y; xlv[q * 4 + 2] = v.z; xlv[q * 4 + 3] = v.w;
        }
        float p = 0.f;
#pragma unroll
        for (int k = 0; k < 16; k++) {
            float tt = xlv[k] + xrr[k];
            tt = (tt > 0.f) ? tt : 0.2f * tt;
            p += attr[k] * tt;
        }
        p += __shfl_xor_sync(0xffffffffu, p, 1);
        p += __shfl_xor_sync(0xffffffffu, p, 2);
        float mn = fmaxf(m, p);
        float scale = __expf(m - mn);
        float w = __expf(p - mn);
        den = den * scale + w;
#pragma unroll
        for (int k = 0; k < 16; k++) acc[k] = acc[k] * scale + w * xlv[k];
        m = mn;
    }

    float inv = 1.f / (den + 1e-16f);
    if (concat) {
        float* op = out + (size_t)warp * DD + fb;
#pragma unroll
        for (int q = 0; q < 4; q++) {
            float4 v;
            v.x = acc[q * 4 + 0] * inv + bias[fb + q * 4 + 0];
            v.y = acc[q * 4 + 1] * inv + bias[fb + q * 4 + 1];
            v.z = acc[q * 4 + 2] * inv + bias[fb + q * 4 + 2];
            v.w = acc[q * 4 + 3] * inv + bias[fb + q * 4 + 3];
            *(float4*)(op + q * 4) = v;
        }
    } else {
        float r[16];
#pragma unroll
        for (int k = 0; k < 16; k++) r[k] = acc[k] * inv;
#pragma unroll
        for (int off = 4; off < 32; off <<= 1)
#pragma unroll
            for (int k = 0; k < 16; k++) r[k] += __shfl_xor_sync(0xffffffffu, r[k], off);
        if (lane < 4) {
            int fo = lane << 4;
            float* op = out + (size_t)warp * FF + fo;
#pragma unroll
            for (int k = 0; k < 16; k++)
                op[k] = r[k] * 0.125f + bias[fo + k];
        }
    }
}

// ---------------- GraphNorm + ReLU (+ optional tf32 rounding of output) ----------------
__global__ void graphnorm_relu_kernel(const float* __restrict__ in, const float* __restrict__ w,
                                      const float* __restrict__ b, const float* __restrict__ ms,
                                      float* __restrict__ out, int D, int round_out) {
    int g = blockIdx.x;
    const float* base = in + (size_t)g * NPG * D;
    float* ob = out + (size_t)g * NPG * D;
    for (int d = threadIdx.x; d < D; d += blockDim.x) {
        float s = 0.f;
#pragma unroll 8
        for (int i = 0; i < NPG; i++) s += base[(size_t)i * D + d];
        float mean = s * (1.f / NPG);
        float msm = ms[d] * mean;
        float v = 0.f;
#pragma unroll 8
        for (int i = 0; i < NPG; i++) { float xc = base[(size_t)i * D + d] - msm; v += xc * xc; }
        v *= (1.f / NPG);
        float invs = rsqrtf(v + 1e-5f);
        float ww = w[d], bb = b[d];
#pragma unroll 8
        for (int i = 0; i < NPG; i++) {
            float xc = base[(size_t)i * D + d] - msm;
            float o = fmaxf(ww * xc * invs + bb, 0.f);
            if (round_out) o = rtf32(o);
            ob[(size_t)i * D + d] = o;
        }
    }
}

// ---------------- global mean pool + final linear ----------------
__global__ void pool_linear_kernel(const float* __restrict__ h, const float* __restrict__ Wlin,
                                   const float* __restrict__ blin, float* __restrict__ out) {
    int g = blockIdx.x;
    __shared__ float p[FF];
    int t = threadIdx.x;
    float s = 0.f;
#pragma unroll 8
    for (int i = 0; i < NPG; i++) s += h[(size_t)(g * NPG + i) * FF + t];
    p[t] = s * (1.f / NPG);
    __syncthreads();
    if (t < 2) {
        float o = blin[t];
#pragma unroll
        for (int f = 0; f < FF; f++) o += p[f] * Wlin[f * 2 + t];
        out[g * 2 + t] = o;
    }
}

// ---------------- host launcher ----------------
extern "C" void kernel_launch(void* const* d_in, const int* in_sizes, int n_in,
                              void* d_out, int out_size) {
    const float* x     = (const float*)d_in[0];
    const int*   esrc  = (const int*)d_in[1];
    const int*   edst  = (const int*)d_in[2];
    const float* Wl[3]  = {(const float*)d_in[4],  (const float*)d_in[11], (const float*)d_in[18]};
    const float* Wr[3]  = {(const float*)d_in[5],  (const float*)d_in[12], (const float*)d_in[19]};
    const float* att[3] = {(const float*)d_in[6],  (const float*)d_in[13], (const float*)d_in[20]};
    const float* bia[3] = {(const float*)d_in[7],  (const float*)d_in[14], (const float*)d_in[21]};
    const float* gnw[3] = {(const float*)d_in[8],  (const float*)d_in[15], (const float*)d_in[22]};
    const float* gnb[3] = {(const float*)d_in[9],  (const float*)d_in[16], (const float*)d_in[23]};
    const float* gnm[3] = {(const float*)d_in[10], (const float*)d_in[17], (const float*)d_in[24]};
    const float* Wlin = (const float*)d_in[25];
    const float* blin = (const float*)d_in[26];
    float* out = (float*)d_out;

    int E = in_sizes[1];

    float *XL, *XR, *A, *B, *Xr, *Wbuf;
    int *cnt, *row, *fill, *csrc;
    cudaGetSymbolAddress((void**)&XL,   g_XL);
    cudaGetSymbolAddress((void**)&XR,   g_XR);
    cudaGetSymbolAddress((void**)&A,    g_A);
    cudaGetSymbolAddress((void**)&B,    g_B);
    cudaGetSymbolAddress((void**)&Xr,   g_Xr);
    cudaGetSymbolAddress((void**)&Wbuf, g_Wr);
    cudaGetSymbolAddress((void**)&cnt,  g_cnt);
    cudaGetSymbolAddress((void**)&row,  g_row);
    cudaGetSymbolAddress((void**)&fill, g_fill);
    cudaGetSymbolAddress((void**)&csrc, g_csrc);

    // rounded weight layout in g_Wr
    float* Wlr[3] = {Wbuf,           Wbuf + 262144, Wbuf + 786432};
    float* Wrr[3] = {Wbuf + 131072,  Wbuf + 524288, Wbuf + 1048576};
    const int wsz[3] = {131072, 262144, 262144};   // per matrix elements

    // ---- tf32 pre-rounding ----
    round4_kernel<<<(NN * 256 / 4 + 255) / 256, 256>>>((const float4*)x, (float4*)Xr, NN * 256 / 4);
    for (int l = 0; l < 3; l++) {
        round4_kernel<<<(wsz[l] / 4 + 255) / 256, 256>>>((const float4*)Wl[l], (float4*)Wlr[l], wsz[l] / 4);
        round4_kernel<<<(wsz[l] / 4 + 255) / 256, 256>>>((const float4*)Wr[l], (float4*)Wrr[l], wsz[l] / 4);
    }

    // ---- build dst-keyed CSR ----
    zero_int_kernel<<<(NN + 255) / 256, 256>>>(cnt, NN);
    count_kernel<<<(E + 255) / 256, 256>>>(edst, E, cnt);
    scan_kernel<<<1, 1024>>>(cnt, row, fill);
    scatter_kernel<<<(E + 255) / 256, 256>>>(esrc, edst, E, fill, csrc);

    dim3 gemm_grid(DD / 128, NN / 128);   // (4, 128)
    const int agg_blocks = (NN * 32) / 256;

    // ---- layer 1 (K=256) ----
    tc_gemm_kernel<<<gemm_grid, 256>>>(256, Xr, Wlr[0], XL);
    tc_gemm_kernel<<<gemm_grid, 256>>>(256, Xr, Wrr[0], XR);
    gat_agg_kernel<<<agg_blocks, 256>>>(XL, XR, row, csrc, att[0], bia[0], A, 1);
    graphnorm_relu_kernel<<<GG, 256>>>(A, gnw[0], gnb[0], gnm[0], B, DD, 1);

    // ---- layer 2 (K=512) ----
    tc_gemm_kernel<<<gemm_grid, 256>>>(DD, B, Wlr[1], XL);
    tc_gemm_kernel<<<gemm_grid, 256>>>(DD, B, Wrr[1], XR);
    gat_agg_kernel<<<agg_blocks, 256>>>(XL, XR, row, csrc, att[1], bia[1], A, 1);
    graphnorm_relu_kernel<<<GG, 256>>>(A, gnw[1], gnb[1], gnm[1], B, DD, 1);

    // ---- layer 3 (K=512, concat=False) ----
    tc_gemm_kernel<<<gemm_grid, 256>>>(DD, B, Wlr[2], XL);
    tc_gemm_kernel<<<gemm_grid, 256>>>(DD, B, Wrr[2], XR);
    gat_agg_kernel<<<agg_blocks, 256>>>(XL, XR, row, csrc, att[2], bia[2], A, 0);
    graphnorm_relu_kernel<<<GG, 256>>>(A, gnw[2], gnb[2], gnm[2], B, FF, 0);

    // ---- pool + linear ----
    pool_linear_kernel<<<GG, 64>>>(B, Wlin, blin, out);
}

// round 4
// speedup vs baseline: 3.0500x; 1.3190x over previous
#include <cuda_runtime.h>
#include <cuda_fp16.h>
#include <math_constants.h>
#include <cstdint>

// ---------------- problem constants ----------------
#define NN 16384      // nodes
#define GG 256        // graphs
#define NPG 64        // nodes per graph
#define FF 64         // per-head features
#define DD 512        // H*F
#define NTOT 1024     // fused Wl|Wr output width
#define EMAX 147456

// ---------------- scratch ----------------
__device__ float  g_XLR[NN * NTOT];     // fused xl|xr GEMM output (fp32)
__device__ float  g_A [NN * DD];        // agg output
__device__ float  g_B [NN * FF];        // layer-3 norm output (fp32, feeds pool)
__device__ __half g_Xh[NN * 256];       // fp16 input x
__device__ __half g_Bh[NN * DD];        // fp16 norm outputs (GEMM input layers 2,3)
__device__ __half g_Wh[1310720];        // fp16 transposed weights [1024][K] x 3 layers
__device__ int    g_cnt [NN];
__device__ int    g_row [NN + 1];
__device__ int    g_fill[NN];
__device__ int    g_csrc[EMAX];

// ---------------- helpers ----------------
__device__ __forceinline__ uint32_t smem_u32(const void* p) {
    return (uint32_t)__cvta_generic_to_shared(p);
}
__device__ __forceinline__ void cp16(uint32_t d, const void* s) {
    asm volatile("cp.async.cg.shared.global [%0], [%1], 16;" :: "r"(d), "l"(s));
}

// ---------------- prep kernels ----------------
__global__ void to_half_kernel(const float4* __restrict__ in, __half2* __restrict__ out, int n4) {
    int i = blockIdx.x * blockDim.x + threadIdx.x;
    if (i < n4) {
        float4 v = in[i];
        out[i * 2]     = __floats2half2_rn(v.x, v.y);
        out[i * 2 + 1] = __floats2half2_rn(v.z, v.w);
    }
}

// W [K, 512] row-major fp32 -> Wt [512, K] K-major fp16
__global__ void transpose_half_kernel(const float* __restrict__ W, __half* __restrict__ Wt, int K) {
    __shared__ float t[32][33];
    int bx = blockIdx.x * 32;   // n
    int by = blockIdx.y * 32;   // k
    int x = threadIdx.x, y = threadIdx.y;
#pragma unroll
    for (int j = 0; j < 32; j += 8) t[y + j][x] = W[(size_t)(by + y + j) * DD + bx + x];
    __syncthreads();
#pragma unroll
    for (int j = 0; j < 32; j += 8)
        Wt[(size_t)(bx + y + j) * K + by + x] = __float2half_rn(t[x][y + j]);
}

// ---------------- CSR build ----------------
__global__ void zero_int_kernel(int* p, int n) {
    int i = blockIdx.x * blockDim.x + threadIdx.x;
    if (i < n) p[i] = 0;
}
__global__ void count_kernel(const int* __restrict__ dst, int E, int* __restrict__ cnt) {
    int e = blockIdx.x * blockDim.x + threadIdx.x;
    if (e < E) atomicAdd(&cnt[dst[e]], 1);
}
__global__ void scan_kernel(const int* __restrict__ cnt, int* __restrict__ row,
                            int* __restrict__ fill) {
    __shared__ int s[1024];
    int tid = threadIdx.x;
    int base = tid * 16;
    int local[16];
    int sum = 0;
#pragma unroll
    for (int i = 0; i < 16; i++) { local[i] = sum; sum += cnt[base + i]; }
    s[tid] = sum;
    __syncthreads();
    for (int off = 1; off < 1024; off <<= 1) {
        int v = (tid >= off) ? s[tid - off] : 0;
        __syncthreads();
        s[tid] += v;
        __syncthreads();
    }
    int pre = (tid == 0) ? 0 : s[tid - 1];
#pragma unroll
    for (int i = 0; i < 16; i++) {
        int o = pre + local[i];
        row[base + i]  = o;
        fill[base + i] = o;
    }
    if (tid == 1023) row[NN] = s[1023];
}
__global__ void scatter_kernel(const int* __restrict__ src, const int* __restrict__ dst,
                               int E, int* __restrict__ fill, int* __restrict__ csrc) {
    int e = blockIdx.x * blockDim.x + threadIdx.x;
    if (e < E) {
        int p = atomicAdd(&fill[dst[e]], 1);
        csrc[p] = src[e];
    }
}

// ---------------- fp16 tensor-core GEMM: C[M,1024] = A[M,K] @ W[1024,K]^T ----------------
// CTA tile 128x128x32, 256 threads, 8 warps (2m x 4n), warp tile 64x32, mma.m16n8k16.
__global__ __launch_bounds__(256, 2)
void hgemm_kernel(int K, const __half* __restrict__ A,
                  const __half* __restrict__ W, float* __restrict__ C) {
    __shared__ __half As[2][128][40];   // stride 40 halfs (80B) -> conflict-free ldmatrix
    __shared__ __half Bs[2][128][40];

    const int tid = threadIdx.x, lane = tid & 31, warp = tid >> 5;
    const int wm = (warp >> 2) << 6;    // 0 / 64
    const int wn = (warp & 3) << 5;     // 0/32/64/96
    const int bm = blockIdx.y << 7, bn = blockIdx.x << 7;

    // load mapping: thread t -> row r = t>>1, half-col sc = (t&1)*16; 2x 16B cp.async each
    const int r = tid >> 1, sc = (tid & 1) << 4;
    const __half* Ag = A + (size_t)(bm + r) * K + sc;
    const __half* Wg = W + (size_t)(bn + r) * K + sc;
    const uint32_t sA = smem_u32(&As[0][0][0]);
    const uint32_t sB = smem_u32(&Bs[0][0][0]);
    const uint32_t dA = sA + (uint32_t)(r * 40 + sc) * 2;
    const uint32_t dB = sB + (uint32_t)(r * 40 + sc) * 2;

#define LOADCHUNK(buf, k0) do {                                  \
        cp16(dA + (buf) * 10240u,       Ag + (k0));              \
        cp16(dA + (buf) * 10240u + 16u, Ag + (k0) + 8);          \
        cp16(dB + (buf) * 10240u,       Wg + (k0));              \
        cp16(dB + (buf) * 10240u + 16u, Wg + (k0) + 8);          \
        asm volatile("cp.async.commit_group;" ::: "memory");     \
    } while (0)

    float c[4][4][4] = {};

    // ldmatrix address components
    const int aRow = wm + (lane & 15);          // + mt*16
    const int aColH = (lane >> 4) << 3;         // + ks*16
    const int bRow0 = wn + ((lane >> 4) << 3) + (lane & 7);   // + p*16
    const int bColH = ((lane >> 3) & 1) << 3;   // + ks*16

    LOADCHUNK(0, 0);

    const int KT = K >> 5;
    for (int kt = 0; kt < KT; kt++) {
        const int buf = kt & 1;
        if (kt + 1 < KT) {
            LOADCHUNK(buf ^ 1, (kt + 1) << 5);
            asm volatile("cp.async.wait_group 1;" ::: "memory");
        } else {
            asm volatile("cp.async.wait_group 0;" ::: "memory");
        }
        __syncthreads();

        const uint32_t aBase = sA + buf * 10240u;
        const uint32_t bBase = sB + buf * 10240u;
#pragma unroll
        for (int ks = 0; ks < 2; ks++) {
            uint32_t a[4][4];
#pragma unroll
            for (int mt = 0; mt < 4; mt++) {
                uint32_t addr = aBase + (uint32_t)((aRow + mt * 16) * 40 + ks * 16 + aColH) * 2;
                asm volatile("ldmatrix.sync.aligned.m8n8.x4.shared.b16 {%0,%1,%2,%3}, [%4];"
                    : "=r"(a[mt][0]), "=r"(a[mt][1]), "=r"(a[mt][2]), "=r"(a[mt][3])
                    : "r"(addr));
            }
            uint32_t b[2][4];
#pragma unroll
            for (int p = 0; p < 2; p++) {
                uint32_t addr = bBase + (uint32_t)((bRow0 + p * 16) * 40 + ks * 16 + bColH) * 2;
                asm volatile("ldmatrix.sync.aligned.m8n8.x4.shared.b16 {%0,%1,%2,%3}, [%4];"
                    : "=r"(b[p][0]), "=r"(b[p][1]), "=r"(b[p][2]), "=r"(b[p][3])
                    : "r"(addr));
            }
#pragma unroll
            for (int mt = 0; mt < 4; mt++)
#pragma unroll
                for (int nt = 0; nt < 4; nt++) {
                    const uint32_t b0 = b[nt >> 1][(nt & 1) * 2];
                    const uint32_t b1 = b[nt >> 1][(nt & 1) * 2 + 1];
                    asm volatile(
                        "mma.sync.aligned.m16n8k16.row.col.f32.f16.f16.f32 "
                        "{%0,%1,%2,%3},{%4,%5,%6,%7},{%8,%9},{%0,%1,%2,%3};"
                        : "+f"(c[mt][nt][0]), "+f"(c[mt][nt][1]),
                          "+f"(c[mt][nt][2]), "+f"(c[mt][nt][3])
                        : "r"(a[mt][0]), "r"(a[mt][1]), "r"(a[mt][2]), "r"(a[mt][3]),
                          "r"(b0), "r"(b1));
                }
        }
        __syncthreads();
    }
#undef LOADCHUNK

    // epilogue
    const int g = lane >> 2, t = lane & 3;
#pragma unroll
    for (int mt = 0; mt < 4; mt++) {
        int r0 = bm + wm + mt * 16 + g;
#pragma unroll
        for (int nt = 0; nt < 4; nt++) {
            int col = bn + wn + nt * 8 + 2 * t;
            *(float2*)(C + (size_t)r0 * NTOT + col)       = make_float2(c[mt][nt][0], c[mt][nt][1]);
            *(float2*)(C + (size_t)(r0 + 8) * NTOT + col) = make_float2(c[mt][nt][2], c[mt][nt][3]);
        }
    }
}

// ---------------- fused GATv2 attention + online-softmax aggregation ----------------
__global__ __launch_bounds__(256)
void gat_agg_kernel(const float* __restrict__ xlr,
                    const int* __restrict__ row, const int* __restrict__ csrc,
                    const float* __restrict__ att, const float* __restrict__ bias,
                    float* __restrict__ out, int concat) {
    int warp = (blockIdx.x * blockDim.x + threadIdx.x) >> 5;
    int lane = threadIdx.x & 31;
    int fb = ((lane >> 2) << 6) + ((lane & 3) << 4);

    float attr[16], xrr[16], acc[16];
    {
        const float4* ap = (const float4*)(att + fb);
        const float4* rp = (const float4*)(xlr + (size_t)warp * NTOT + 512 + fb);
#pragma unroll
        for (int q = 0; q < 4; q++) {
            float4 a = ap[q];
            attr[q * 4 + 0] = a.x; attr[q * 4 + 1] = a.y; attr[q * 4 + 2] = a.z; attr[q * 4 + 3] = a.w;
            float4 r = rp[q];
            xrr[q * 4 + 0] = r.x; xrr[q * 4 + 1] = r.y; xrr[q * 4 + 2] = r.z; xrr[q * 4 + 3] = r.w;
        }
    }
#pragma unroll
    for (int k = 0; k < 16; k++) acc[k] = 0.f;

    float m = -CUDART_INF_F, den = 0.f;
    int j0 = row[warp], j1 = row[warp + 1];

    for (int j = j0; j < j1; j++) {
        int s = csrc[j];
        float xlv[16];
        const float4* lp = (const float4*)(xlr + (size_t)s * NTOT + fb);
#pragma unroll
        for (int q = 0; q < 4; q++) {
            float4 v = lp[q];
            xlv[q * 4 + 0] = v.x; xlv[q * 4 + 1] = v.y; xlv[q * 4 + 2] = v.z; xlv[q * 4 + 3] = v.w;
        }
        float p = 0.f;
#pragma unroll
        for (int k = 0; k < 16; k++) {
            float tt = xlv[k] + xrr[k];
            tt = (tt > 0.f) ? tt : 0.2f * tt;
            p += attr[k] * tt;
        }
        p += __shfl_xor_sync(0xffffffffu, p, 1);
        p += __shfl_xor_sync(0xffffffffu, p, 2);
        float mn = fmaxf(m, p);
        float scale = __expf(m - mn);
        float w = __expf(p - mn);
        den = den * scale + w;
#pragma unroll
        for (int k = 0; k < 16; k++) acc[k] = acc[k] * scale + w * xlv[k];
        m = mn;
    }

    float inv = 1.f / (den + 1e-16f);
    if (concat) {
        float* op = out + (size_t)warp * DD + fb;
#pragma unroll
        for (int q = 0; q < 4; q++) {
            float4 v;
            v.x = acc[q * 4 + 0] * inv + bias[fb + q * 4 + 0];
            v.y = acc[q * 4 + 1] * inv + bias[fb + q * 4 + 1];
            v.z = acc[q * 4 + 2] * inv + bias[fb + q * 4 + 2];
            v.w = acc[q * 4 + 3] * inv + bias[fb + q * 4 + 3];
            *(float4*)(op + q * 4) = v;
        }
    } else {
        float r[16];
#pragma unroll
        for (int k = 0; k < 16; k++) r[k] = acc[k] * inv;
#pragma unroll
        for (int off = 4; off < 32; off <<= 1)
#pragma unroll
            for (int k = 0; k < 16; k++) r[k] += __shfl_xor_sync(0xffffffffu, r[k], off);
        if (lane < 4) {
            int fo = lane << 4;
            float* op = out + (size_t)warp * FF + fo;
#pragma unroll
            for (int k = 0; k < 16; k++)
                op[k] = r[k] * 0.125f + bias[fo + k];
        }
    }
}

// ---------------- GraphNorm + ReLU; mode 0 -> fp32 out, mode 1 -> fp16 out ----------------
__global__ void graphnorm_relu_kernel(const float* __restrict__ in, const float* __restrict__ w,
                                      const float* __restrict__ b, const float* __restrict__ ms,
                                      float* __restrict__ outf, __half* __restrict__ outh,
                                      int D, int mode) {
    int g = blockIdx.x;
    const float* base = in + (size_t)g * NPG * D;
    for (int d = threadIdx.x; d < D; d += blockDim.x) {
        float s = 0.f;
#pragma unroll 8
        for (int i = 0; i < NPG; i++) s += base[(size_t)i * D + d];
        float mean = s * (1.f / NPG);
        float msm = ms[d] * mean;
        float v = 0.f;
#pragma unroll 8
        for (int i = 0; i < NPG; i++) { float xc = base[(size_t)i * D + d] - msm; v += xc * xc; }
        v *= (1.f / NPG);
        float invs = rsqrtf(v + 1e-5f);
        float ww = w[d], bb = b[d];
        if (mode == 1) {
            __half* ob = outh + (size_t)g * NPG * D;
#pragma unroll 8
            for (int i = 0; i < NPG; i++) {
                float xc = base[(size_t)i * D + d] - msm;
                float o = fmaxf(ww * xc * invs + bb, 0.f);
                ob[(size_t)i * D + d] = __float2half_rn(o);
            }
        } else {
            float* ob = outf + (size_t)g * NPG * D;
#pragma unroll 8
            for (int i = 0; i < NPG; i++) {
                float xc = base[(size_t)i * D + d] - msm;
                ob[(size_t)i * D + d] = fmaxf(ww * xc * invs + bb, 0.f);
            }
        }
    }
}

// ---------------- global mean pool + final linear ----------------
__global__ void pool_linear_kernel(const float* __restrict__ h, const float* __restrict__ Wlin,
                                   const float* __restrict__ blin, float* __restrict__ out) {
    int g = blockIdx.x;
    __shared__ float p[FF];
    int t = threadIdx.x;
    float s = 0.f;
#pragma unroll 8
    for (int i = 0; i < NPG; i++) s += h[(size_t)(g * NPG + i) * FF + t];
    p[t] = s * (1.f / NPG);
    __syncthreads();
    if (t < 2) {
        float o = blin[t];
#pragma unroll
        for (int f = 0; f < FF; f++) o += p[f] * Wlin[f * 2 + t];
        out[g * 2 + t] = o;
    }
}

// ---------------- host launcher ----------------
extern "C" void kernel_launch(void* const* d_in, const int* in_sizes, int n_in,
                              void* d_out, int out_size) {
    const float* x     = (const float*)d_in[0];
    const int*   esrc  = (const int*)d_in[1];
    const int*   edst  = (const int*)d_in[2];
    const float* Wl[3]  = {(const float*)d_in[4],  (const float*)d_in[11], (const float*)d_in[18]};
    const float* Wr[3]  = {(const float*)d_in[5],  (const float*)d_in[12], (const float*)d_in[19]};
    const float* att[3] = {(const float*)d_in[6],  (const float*)d_in[13], (const float*)d_in[20]};
    const float* bia[3] = {(const float*)d_in[7],  (const float*)d_in[14], (const float*)d_in[21]};
    const float* gnw[3] = {(const float*)d_in[8],  (const float*)d_in[15], (const float*)d_in[22]};
    const float* gnb[3] = {(const float*)d_in[9],  (const float*)d_in[16], (const float*)d_in[23]};
    const float* gnm[3] = {(const float*)d_in[10], (const float*)d_in[17], (const float*)d_in[24]};
    const float* Wlin = (const float*)d_in[25];
    const float* blin = (const float*)d_in[26];
    float* out = (float*)d_out;

    int E = in_sizes[1];

    float *XLR, *A, *B;
    __half *Xh, *Bh, *Wh;
    int *cnt, *row, *fill, *csrc;
    cudaGetSymbolAddress((void**)&XLR, g_XLR);
    cudaGetSymbolAddress((void**)&A,   g_A);
    cudaGetSymbolAddress((void**)&B,   g_B);
    cudaGetSymbolAddress((void**)&Xh,  g_Xh);
    cudaGetSymbolAddress((void**)&Bh,  g_Bh);
    cudaGetSymbolAddress((void**)&Wh,  g_Wh);
    cudaGetSymbolAddress((void**)&cnt, g_cnt);
    cudaGetSymbolAddress((void**)&row, g_row);
    cudaGetSymbolAddress((void**)&fill,g_fill);
    cudaGetSymbolAddress((void**)&csrc,g_csrc);

    // weight prep: transpose + fp16 into [1024, K] per layer
    const int Koff[3] = {256, 512, 512};
    __half* WhL[3] = {Wh, Wh + 262144, Wh + 786432};
    for (int l = 0; l < 3; l++) {
        int K = Koff[l];
        dim3 tg(16, K / 32), tb(32, 8);
        transpose_half_kernel<<<tg, tb>>>(Wl[l], WhL[l], K);
        transpose_half_kernel<<<tg, tb>>>(Wr[l], WhL[l] + 512 * K, K);
    }
    to_half_kernel<<<(NN * 256 / 4 + 255) / 256, 256>>>((const float4*)x, (__half2*)Xh, NN * 256 / 4);

    // CSR build
    zero_int_kernel<<<(NN + 255) / 256, 256>>>(cnt, NN);
    count_kernel<<<(E + 255) / 256, 256>>>(edst, E, cnt);
    scan_kernel<<<1, 1024>>>(cnt, row, fill);
    scatter_kernel<<<(E + 255) / 256, 256>>>(esrc, edst, E, fill, csrc);

    dim3 ggrid(NTOT / 128, NN / 128);     // (8, 128)
    const int agg_blocks = (NN * 32) / 256;

    // layer 1 (K=256)
    hgemm_kernel<<<ggrid, 256>>>(256, Xh, WhL[0], XLR);
    gat_agg_kernel<<<agg_blocks, 256>>>(XLR, row, csrc, att[0], bia[0], A, 1);
    graphnorm_relu_kernel<<<GG, 256>>>(A, gnw[0], gnb[0], gnm[0], nullptr, Bh, DD, 1);

    // layer 2 (K=512)
    hgemm_kernel<<<ggrid, 256>>>(512, Bh, WhL[1], XLR);
    gat_agg_kernel<<<agg_blocks, 256>>>(XLR, row, csrc, att[1], bia[1], A, 1);
    graphnorm_relu_kernel<<<GG, 256>>>(A, gnw[1], gnb[1], gnm[1], nullptr, Bh, DD, 1);

    // layer 3 (K=512, concat=False)
    hgemm_kernel<<<ggrid, 256>>>(512, Bh, WhL[2], XLR);
    gat_agg_kernel<<<agg_blocks, 256>>>(XLR, row, csrc, att[2], bia[2], A, 0);
    graphnorm_relu_kernel<<<GG, 256>>>(A, gnw[2], gnb[2], gnm[2], B, nullptr, FF, 0);

    // pool + linear
    pool_linear_kernel<<<GG, 64>>>(B, Wlin, blin, out);
}